// round 10
// baseline (speedup 1.0000x reference)
#include <cuda_runtime.h>
#include <math.h>
#include <stdint.h>

// ---------------------------------------------------------------------------
// GraphProjection: 80000 points, 3 cameras, feature pyramid (64/128/256/512 ch)
// out[p] = [coord(3) | max over views(960) | mean(960) | std(960)] -> 2883 f32
// Round 10: shifted-window aligned STG.128, but the window shift is applied to
//   the STATS (stats are elementwise, so shift commutes). Loads die before the
//   shuffles -> low register pressure, high occupancy. Lane-31 cross-warp
//   neighbor delivered via a tiny smem handoff (no second gather path).
// ---------------------------------------------------------------------------

#define MAX_N 80000
#define OUT_STRIDE 2883

__device__ int g_off[MAX_N * 12];   // [point][view*4 + scale] flat float offset

struct CamData {
    float B0[9];     // inv(c0^T)
    float c[3][9];   // per-view rotation rows (X,Y,Z normalized)
    float o[3][3];   // per-view camera origin (unnormalized Z)
};

// --- camera matrix, mirroring jnp fp32 op order -----------------------------
__device__ __forceinline__ void cam_mat(const float* prm, float* Crow, float* O) {
    const float PI = 3.14159265358979323846f;
    float theta = prm[0] * PI / 180.0f;
    float e     = prm[1] * PI / 180.0f;
    float camy  = prm[3] * sinf(e);
    float lens  = prm[3] * cosf(e);
    float camx  = lens * cosf(theta);
    float camz  = lens * sinf(theta);

    float Zv[3] = { camx, camy, camz };
    float Yv[3] = { camy * cosf(theta + PI), lens, camy * sinf(theta + PI) };
    float Xv[3] = { Yv[1]*Zv[2] - Yv[2]*Zv[1],
                    Yv[2]*Zv[0] - Yv[0]*Zv[2],
                    Yv[0]*Zv[1] - Yv[1]*Zv[0] };

    float nx = sqrtf(Xv[0]*Xv[0] + Xv[1]*Xv[1] + Xv[2]*Xv[2]);
    float ny = sqrtf(Yv[0]*Yv[0] + Yv[1]*Yv[1] + Yv[2]*Yv[2]);
    float nz = sqrtf(Zv[0]*Zv[0] + Zv[1]*Zv[1] + Zv[2]*Zv[2]);
    for (int k = 0; k < 3; k++) {
        Crow[0*3 + k] = __fdiv_rn(Xv[k], nx);
        Crow[1*3 + k] = __fdiv_rn(Yv[k], ny);
        Crow[2*3 + k] = __fdiv_rn(Zv[k], nz);
        O[k] = Zv[k];
    }
}

// --- kernel A: per-block camera setup (incl. DP inverse) + per-point offsets
__global__ __launch_bounds__(256)
void proj_kernel(const float* __restrict__ coord,
                 const float* __restrict__ cams, int N) {
    __shared__ CamData cam;

    if (threadIdx.x == 0) {
        for (int i = 0; i < 3; i++)
            cam_mat(cams + i * 5, cam.c[i], cam.o[i]);

        double M[3][3];
        for (int r = 0; r < 3; r++)
            for (int k = 0; k < 3; k++)
                M[r][k] = (double)cam.c[0][k*3 + r];

        double det = M[0][0]*(M[1][1]*M[2][2] - M[1][2]*M[2][1])
                   - M[0][1]*(M[1][0]*M[2][2] - M[1][2]*M[2][0])
                   + M[0][2]*(M[1][0]*M[2][1] - M[1][1]*M[2][0]);
        double inv[3][3];
        inv[0][0] =  (M[1][1]*M[2][2] - M[1][2]*M[2][1]) / det;
        inv[0][1] =  (M[0][2]*M[2][1] - M[0][1]*M[2][2]) / det;
        inv[0][2] =  (M[0][1]*M[1][2] - M[0][2]*M[1][1]) / det;
        inv[1][0] =  (M[1][2]*M[2][0] - M[1][0]*M[2][2]) / det;
        inv[1][1] =  (M[0][0]*M[2][2] - M[0][2]*M[2][0]) / det;
        inv[1][2] =  (M[0][2]*M[1][0] - M[0][0]*M[1][2]) / det;
        inv[2][0] =  (M[1][0]*M[2][1] - M[1][1]*M[2][0]) / det;
        inv[2][1] =  (M[0][1]*M[2][0] - M[0][0]*M[2][1]) / det;
        inv[2][2] =  (M[0][0]*M[1][1] - M[0][1]*M[1][0]) / det;
        for (int k = 0; k < 3; k++)
            for (int j = 0; j < 3; j++)
                cam.B0[k*3 + j] = (float)inv[k][j];
    }
    __syncthreads();

    int p = blockIdx.x * blockDim.x + threadIdx.x;
    if (p >= N) return;

    float x = coord[p*3 + 0];
    float y = coord[p*3 + 1];
    float z = coord[p*3 + 2];

    float po[3];
    #pragma unroll
    for (int j = 0; j < 3; j++)
        po[j] = x * cam.B0[0*3 + j] + y * cam.B0[1*3 + j]
              + z * cam.B0[2*3 + j] + cam.o[0][j];

    const int   ds[4] = { 56, 28, 14, 7 };
    const int   Cs[4] = { 64, 128, 256, 512 };
    const float qi[4] = { 0.25f, 0.125f, 0.0625f, 0.03125f };  // d/224 exact pow2

    int off[12];
    #pragma unroll
    for (int i = 0; i < 3; i++) {
        float vx = po[0] - cam.o[i][0];
        float vy = po[1] - cam.o[i][1];
        float vz = po[2] - cam.o[i][2];
        const float* C = cam.c[i];
        float X  = vx*C[0] + vy*C[1] + vz*C[2];
        float Y  = vx*C[3] + vy*C[4] + vz*C[5];
        float Zc = vx*C[6] + vy*C[7] + vz*C[8];

        float negz = -Zc;
        float h = __fdiv_rn(248.0f * (-Y), negz) + 112.0f;
        float w = __fdiv_rn(248.0f * X,    negz) + 112.0f;
        h = fminf(fmaxf(h, 0.0f), 223.0f);
        w = fminf(fmaxf(w, 0.0f), 223.0f);

        #pragma unroll
        for (int s = 0; s < 4; s++) {
            int ih = (int)(h * qi[s]);
            int iw = (int)(w * qi[s]);
            off[i*4 + s] = (ih * ds[s] + iw) * Cs[s];
        }
    }
    int4* dst = reinterpret_cast<int4*>(g_off + p*12);
    dst[0] = make_int4(off[0], off[1], off[2],  off[3]);
    dst[1] = make_int4(off[4], off[5], off[6],  off[7]);
    dst[2] = make_int4(off[8], off[9], off[10], off[11]);
}

// channel -> (feature tensor, scale idx, local channel)
__device__ __forceinline__ void map_ch(int c, const float* f1, const float* f2,
                                       const float* f3, const float* f4,
                                       const float*& f, int& s, int& cl) {
    if (c < 64)       { s = 0; f = f1; cl = c; }
    else if (c < 192) { s = 1; f = f2; cl = c - 64; }
    else if (c < 448) { s = 2; f = f3; cl = c - 192; }
    else              { s = 3; f = f4; cl = c - 448; }
}

// window [sh, sh+4) over (v[0..3], n[0..2])
__device__ __forceinline__ float4 shiftwin(int sh, const float v[4], const float n[3]) {
    switch (sh) {
        case 0:  return make_float4(v[0], v[1], v[2], v[3]);
        case 1:  return make_float4(v[1], v[2], v[3], n[0]);
        case 2:  return make_float4(v[2], v[3], n[0], n[1]);
        default: return make_float4(v[3], n[0], n[1], n[2]);
    }
}

// --- kernel B: stats-then-shift gather, aligned STG.128 ---------------------
__global__ __launch_bounds__(256)
void gather_kernel(const float* __restrict__ f1, const float* __restrict__ f2,
                   const float* __restrict__ f3, const float* __restrict__ f4,
                   const float* __restrict__ coord, float* __restrict__ out) {
    unsigned p = blockIdx.x;
    int t = threadIdx.x;
    int lane = t & 31;

    __shared__ int   soff[12];
    __shared__ float sstat[7][9];   // warp-boundary stat handoff

    if (t < 12) soff[t] = g_off[p*12 + t];
    __syncthreads();

    unsigned g = p * (unsigned)OUT_STRIDE;          // < 2^31
    int sh = (int)((4u - ((g + 3u) & 3u)) & 3u);    // g+3+sh ≡ 0 (mod 4)

    // all 256 threads run the main path (convergent shuffles); q clamped
    int q  = min(t, 239);
    int c4 = q * 4;

    // ---- load own quads, compute stats immediately (loads die here) ----
    float mxv[4], mnv[4], sdv[4];
    {
        const float* fa; int sa, cla;
        map_ch(c4, f1, f2, f3, f4, fa, sa, cla);
        float4 A0 = __ldg(reinterpret_cast<const float4*>(fa + soff[0 + sa] + cla));
        float4 A1 = __ldg(reinterpret_cast<const float4*>(fa + soff[4 + sa] + cla));
        float4 A2 = __ldg(reinterpret_cast<const float4*>(fa + soff[8 + sa] + cla));
        float av[4] = { A0.x, A0.y, A0.z, A0.w };
        float bv[4] = { A1.x, A1.y, A1.z, A1.w };
        float dv[4] = { A2.x, A2.y, A2.z, A2.w };
        #pragma unroll
        for (int k = 0; k < 4; k++) {
            float aa = av[k], bb = bv[k], dd = dv[k];
            mxv[k] = fmaxf(aa, fmaxf(bb, dd));
            float mn = (aa + bb + dd) * (1.0f / 3.0f);
            mnv[k] = mn;
            float da = aa - mn, db = bb - mn, dc = dd - mn;
            sdv[k] = sqrtf((da*da + db*db + dc*dc) * (1.0f / 3.0f));
        }
    }

    // ---- neighbor stats (first 3 of thread t+1's quads) ----
    float nmx[3] = {0,0,0}, nmn[3] = {0,0,0}, nsd[3] = {0,0,0};
    if (sh) {   // block-uniform branch
        #pragma unroll
        for (int j = 0; j < 3; j++) {
            nmx[j] = __shfl_down_sync(0xFFFFFFFFu, mxv[j], 1);
            nmn[j] = __shfl_down_sync(0xFFFFFFFFu, mnv[j], 1);
            nsd[j] = __shfl_down_sync(0xFFFFFFFFu, sdv[j], 1);
        }
        // thread 32w (w=1..7) publishes for warp w-1's lane 31
        if (lane == 0 && t > 0) {
            float* sp = sstat[(t >> 5) - 1];
            sp[0] = mxv[0]; sp[1] = mxv[1]; sp[2] = mxv[2];
            sp[3] = mnv[0]; sp[4] = mnv[1]; sp[5] = mnv[2];
            sp[6] = sdv[0]; sp[7] = sdv[1]; sp[8] = sdv[2];
        }
        __syncthreads();
        if (lane == 31 && t < 239) {
            const float* sp = sstat[t >> 5];
            nmx[0] = sp[0]; nmx[1] = sp[1]; nmx[2] = sp[2];
            nmn[0] = sp[3]; nmn[1] = sp[4]; nmn[2] = sp[5];
            nsd[0] = sp[6]; nsd[1] = sp[7]; nsd[2] = sp[8];
        }
    }

    // ---- aligned STG.128 stores ----
    bool store_ok = sh ? (t < 239) : (t < 240);
    if (store_ok) {
        float* base = out + (g + 3u + (unsigned)(sh + c4));
        *reinterpret_cast<float4*>(base)        = shiftwin(sh, mxv, nmx);
        *reinterpret_cast<float4*>(base + 960)  = shiftwin(sh, mnv, nmn);
        *reinterpret_cast<float4*>(base + 1920) = shiftwin(sh, sdv, nsd);
    }

    // ---- edges + coord (threads 240..255) ----
    if (t >= 240) {
        int h = t - 240;                       // 0..15
        if (sh && h < 4) {
            int ch = (h < sh) ? h : (956 + sh + (h - sh));
            const float* f; int ss, cl;
            map_ch(ch, f1, f2, f3, f4, f, ss, cl);
            float a = __ldg(f + soff[0 + ss] + cl);
            float b = __ldg(f + soff[4 + ss] + cl);
            float d = __ldg(f + soff[8 + ss] + cl);
            float mx = fmaxf(a, fmaxf(b, d));
            float mn = (a + b + d) * (1.0f / 3.0f);
            float da = a - mn, db = b - mn, dc = d - mn;
            float sd = sqrtf((da*da + db*db + dc*dc) * (1.0f / 3.0f));
            out[g + 3u + (unsigned)ch]    = mx;
            out[g + 963u + (unsigned)ch]  = mn;
            out[g + 1923u + (unsigned)ch] = sd;
        }
        if (h >= 8 && h < 11)                  // coord passthrough
            out[g + (unsigned)(h - 8)] = __ldg(coord + p*3 + (h - 8));
    }
}

extern "C" void kernel_launch(void* const* d_in, const int* in_sizes, int n_in,
                              void* d_out, int out_size) {
    const float* coord = (const float*)d_in[0];
    const float* cams  = (const float*)d_in[1];
    const float* f1    = (const float*)d_in[2];
    const float* f2    = (const float*)d_in[3];
    const float* f3    = (const float*)d_in[4];
    const float* f4    = (const float*)d_in[5];
    float* out = (float*)d_out;

    int N = in_sizes[0] / 3;

    proj_kernel<<<(N + 255) / 256, 256>>>(coord, cams, N);
    gather_kernel<<<N, 256>>>(f1, f2, f3, f4, coord, out);
}

// round 11
// speedup vs baseline: 1.2241x; 1.2241x over previous
#include <cuda_runtime.h>
#include <math.h>
#include <stdint.h>

// ---------------------------------------------------------------------------
// GraphProjection: 80000 points, 3 cameras, feature pyramid (64/128/256/512 ch)
// out[p] = [coord(3) | max over views(960) | mean(960) | std(960)] -> 2883 f32
// Round 11: revert to R6 structure (best: 190us), then remove its latency
//   limiters: no __syncthreads (warp-local offset fetch + shfl broadcast),
//   2 points per block (double MLP, half the blocks).
// ---------------------------------------------------------------------------

#define MAX_N 80000
#define OUT_STRIDE 2883

__device__ int g_off[MAX_N * 12];   // [point][view*4 + scale] flat float offset

struct CamData {
    float B0[9];     // inv(c0^T)
    float c[3][9];   // per-view rotation rows (X,Y,Z normalized)
    float o[3][3];   // per-view camera origin (unnormalized Z)
};

// --- camera matrix, mirroring jnp fp32 op order -----------------------------
__device__ __forceinline__ void cam_mat(const float* prm, float* Crow, float* O) {
    const float PI = 3.14159265358979323846f;
    float theta = prm[0] * PI / 180.0f;
    float e     = prm[1] * PI / 180.0f;
    float camy  = prm[3] * sinf(e);
    float lens  = prm[3] * cosf(e);
    float camx  = lens * cosf(theta);
    float camz  = lens * sinf(theta);

    float Zv[3] = { camx, camy, camz };
    float Yv[3] = { camy * cosf(theta + PI), lens, camy * sinf(theta + PI) };
    float Xv[3] = { Yv[1]*Zv[2] - Yv[2]*Zv[1],
                    Yv[2]*Zv[0] - Yv[0]*Zv[2],
                    Yv[0]*Zv[1] - Yv[1]*Zv[0] };

    float nx = sqrtf(Xv[0]*Xv[0] + Xv[1]*Xv[1] + Xv[2]*Xv[2]);
    float ny = sqrtf(Yv[0]*Yv[0] + Yv[1]*Yv[1] + Yv[2]*Yv[2]);
    float nz = sqrtf(Zv[0]*Zv[0] + Zv[1]*Zv[1] + Zv[2]*Zv[2]);
    for (int k = 0; k < 3; k++) {
        Crow[0*3 + k] = __fdiv_rn(Xv[k], nx);
        Crow[1*3 + k] = __fdiv_rn(Yv[k], ny);
        Crow[2*3 + k] = __fdiv_rn(Zv[k], nz);
        O[k] = Zv[k];
    }
}

// --- kernel A: per-block camera setup (incl. DP inverse) + per-point offsets
__global__ __launch_bounds__(256)
void proj_kernel(const float* __restrict__ coord,
                 const float* __restrict__ cams, int N) {
    __shared__ CamData cam;

    if (threadIdx.x == 0) {
        for (int i = 0; i < 3; i++)
            cam_mat(cams + i * 5, cam.c[i], cam.o[i]);

        double M[3][3];
        for (int r = 0; r < 3; r++)
            for (int k = 0; k < 3; k++)
                M[r][k] = (double)cam.c[0][k*3 + r];

        double det = M[0][0]*(M[1][1]*M[2][2] - M[1][2]*M[2][1])
                   - M[0][1]*(M[1][0]*M[2][2] - M[1][2]*M[2][0])
                   + M[0][2]*(M[1][0]*M[2][1] - M[1][1]*M[2][0]);
        double inv[3][3];
        inv[0][0] =  (M[1][1]*M[2][2] - M[1][2]*M[2][1]) / det;
        inv[0][1] =  (M[0][2]*M[2][1] - M[0][1]*M[2][2]) / det;
        inv[0][2] =  (M[0][1]*M[1][2] - M[0][2]*M[1][1]) / det;
        inv[1][0] =  (M[1][2]*M[2][0] - M[1][0]*M[2][2]) / det;
        inv[1][1] =  (M[0][0]*M[2][2] - M[0][2]*M[2][0]) / det;
        inv[1][2] =  (M[0][2]*M[1][0] - M[0][0]*M[1][2]) / det;
        inv[2][0] =  (M[1][0]*M[2][1] - M[1][1]*M[2][0]) / det;
        inv[2][1] =  (M[0][1]*M[2][0] - M[0][0]*M[2][1]) / det;
        inv[2][2] =  (M[0][0]*M[1][1] - M[0][1]*M[1][0]) / det;
        for (int k = 0; k < 3; k++)
            for (int j = 0; j < 3; j++)
                cam.B0[k*3 + j] = (float)inv[k][j];
    }
    __syncthreads();

    int p = blockIdx.x * blockDim.x + threadIdx.x;
    if (p >= N) return;

    float x = coord[p*3 + 0];
    float y = coord[p*3 + 1];
    float z = coord[p*3 + 2];

    float po[3];
    #pragma unroll
    for (int j = 0; j < 3; j++)
        po[j] = x * cam.B0[0*3 + j] + y * cam.B0[1*3 + j]
              + z * cam.B0[2*3 + j] + cam.o[0][j];

    const int   ds[4] = { 56, 28, 14, 7 };
    const int   Cs[4] = { 64, 128, 256, 512 };
    const float qi[4] = { 0.25f, 0.125f, 0.0625f, 0.03125f };  // d/224 exact pow2

    int off[12];
    #pragma unroll
    for (int i = 0; i < 3; i++) {
        float vx = po[0] - cam.o[i][0];
        float vy = po[1] - cam.o[i][1];
        float vz = po[2] - cam.o[i][2];
        const float* C = cam.c[i];
        float X  = vx*C[0] + vy*C[1] + vz*C[2];
        float Y  = vx*C[3] + vy*C[4] + vz*C[5];
        float Zc = vx*C[6] + vy*C[7] + vz*C[8];

        float negz = -Zc;
        float h = __fdiv_rn(248.0f * (-Y), negz) + 112.0f;
        float w = __fdiv_rn(248.0f * X,    negz) + 112.0f;
        h = fminf(fmaxf(h, 0.0f), 223.0f);
        w = fminf(fmaxf(w, 0.0f), 223.0f);

        #pragma unroll
        for (int s = 0; s < 4; s++) {
            int ih = (int)(h * qi[s]);
            int iw = (int)(w * qi[s]);
            off[i*4 + s] = (ih * ds[s] + iw) * Cs[s];
        }
    }
    int4* dst = reinterpret_cast<int4*>(g_off + p*12);
    dst[0] = make_int4(off[0], off[1], off[2],  off[3]);
    dst[1] = make_int4(off[4], off[5], off[6],  off[7]);
    dst[2] = make_int4(off[8], off[9], off[10], off[11]);
}

// --- kernel B: 2 points/block, barrier-free, warp-local offsets -------------
__global__ __launch_bounds__(256)
void gather_kernel(const float* __restrict__ f1, const float* __restrict__ f2,
                   const float* __restrict__ f3, const float* __restrict__ f4,
                   const float* __restrict__ coord, float* __restrict__ out) {
    unsigned p0   = 2u * blockIdx.x;            // points p0, p0+1
    int t    = threadIdx.x;
    int wid  = t >> 5;
    int lane = t & 31;

    // each warp fetches both points' 12 offsets (24 contiguous ints)
    int v = 0;
    if (lane < 24) v = g_off[p0 * 12 + lane];

    unsigned g0 = p0 * (unsigned)OUT_STRIDE;

    if (t < 6) {   // coord passthrough: t 0..2 -> p0, 3..5 -> p1
        int j = t / 3, k = t - 3 * j;
        out[g0 + (unsigned)j * OUT_STRIDE + k] = __ldg(coord + (p0 + j) * 3 + k);
    }

    // 30 channel-rows of 32; warp w handles rows w, w+8, w+16, w+24
    #pragma unroll
    for (int i = 0; i < 4; i++) {
        int r = wid + (i << 3);
        if (r >= 30) break;
        int c = (r << 5) + lane;

        const float* f;
        int base, s;
        if (c < 64)       { s = 0; f = f1; base = 0; }
        else if (c < 192) { s = 1; f = f2; base = 64; }
        else if (c < 448) { s = 2; f = f3; base = 192; }
        else              { s = 3; f = f4; base = 448; }
        int cl = c - base;

        #pragma unroll
        for (int j = 0; j < 2; j++) {
            int o0 = __shfl_sync(0xFFFFFFFFu, v, j * 12 + s);
            int o1 = __shfl_sync(0xFFFFFFFFu, v, j * 12 + 4 + s);
            int o2 = __shfl_sync(0xFFFFFFFFu, v, j * 12 + 8 + s);

            float a = __ldg(f + o0 + cl);
            float b = __ldg(f + o1 + cl);
            float d = __ldg(f + o2 + cl);

            float mx = fmaxf(a, fmaxf(b, d));
            float mn = (a + b + d) * (1.0f / 3.0f);
            float da = a - mn, db = b - mn, dc = d - mn;
            float sd = sqrtf((da*da + db*db + dc*dc) * (1.0f / 3.0f));

            unsigned g = g0 + (unsigned)j * OUT_STRIDE + (unsigned)c;
            out[g + 3u]    = mx;
            out[g + 963u]  = mn;
            out[g + 1923u] = sd;
        }
    }
}

extern "C" void kernel_launch(void* const* d_in, const int* in_sizes, int n_in,
                              void* d_out, int out_size) {
    const float* coord = (const float*)d_in[0];
    const float* cams  = (const float*)d_in[1];
    const float* f1    = (const float*)d_in[2];
    const float* f2    = (const float*)d_in[3];
    const float* f3    = (const float*)d_in[4];
    const float* f4    = (const float*)d_in[5];
    float* out = (float*)d_out;

    int N = in_sizes[0] / 3;

    proj_kernel<<<(N + 255) / 256, 256>>>(coord, cams, N);
    gather_kernel<<<N / 2, 256>>>(f1, f2, f3, f4, coord, out);
}

// round 12
// speedup vs baseline: 1.2966x; 1.0592x over previous
#include <cuda_runtime.h>
#include <math.h>
#include <stdint.h>

// ---------------------------------------------------------------------------
// GraphProjection: 80000 points, 3 cameras, feature pyramid (64/128/256/512 ch)
// out[p] = [coord(3) | max over views(960) | mean(960) | std(960)] -> 2883 f32
// Round 12: warp-per-point rolling window. Warp walks 30 aligned channel rows;
//   stores go out through a u-shifted window rebuilt from (prev,cur) stats via
//   ONE warp-local shuffle per stat -> ALL loads and ALL stores are 128B-line
//   aligned (1 wavefront each). ~185 wf/point vs 270 in R11. No barriers.
// ---------------------------------------------------------------------------

#define MAX_N 80000
#define OUT_STRIDE 2883

__device__ int g_off[MAX_N * 12];   // [point][view*4 + scale] flat float offset

struct CamData {
    float B0[9];     // inv(c0^T)
    float c[3][9];   // per-view rotation rows (X,Y,Z normalized)
    float o[3][3];   // per-view camera origin (unnormalized Z)
};

// --- camera matrix, mirroring jnp fp32 op order -----------------------------
__device__ __forceinline__ void cam_mat(const float* prm, float* Crow, float* O) {
    const float PI = 3.14159265358979323846f;
    float theta = prm[0] * PI / 180.0f;
    float e     = prm[1] * PI / 180.0f;
    float camy  = prm[3] * sinf(e);
    float lens  = prm[3] * cosf(e);
    float camx  = lens * cosf(theta);
    float camz  = lens * sinf(theta);

    float Zv[3] = { camx, camy, camz };
    float Yv[3] = { camy * cosf(theta + PI), lens, camy * sinf(theta + PI) };
    float Xv[3] = { Yv[1]*Zv[2] - Yv[2]*Zv[1],
                    Yv[2]*Zv[0] - Yv[0]*Zv[2],
                    Yv[0]*Zv[1] - Yv[1]*Zv[0] };

    float nx = sqrtf(Xv[0]*Xv[0] + Xv[1]*Xv[1] + Xv[2]*Xv[2]);
    float ny = sqrtf(Yv[0]*Yv[0] + Yv[1]*Yv[1] + Yv[2]*Yv[2]);
    float nz = sqrtf(Zv[0]*Zv[0] + Zv[1]*Zv[1] + Zv[2]*Zv[2]);
    for (int k = 0; k < 3; k++) {
        Crow[0*3 + k] = __fdiv_rn(Xv[k], nx);
        Crow[1*3 + k] = __fdiv_rn(Yv[k], ny);
        Crow[2*3 + k] = __fdiv_rn(Zv[k], nz);
        O[k] = Zv[k];
    }
}

// --- kernel A: per-block camera setup (incl. DP inverse) + per-point offsets
__global__ __launch_bounds__(256)
void proj_kernel(const float* __restrict__ coord,
                 const float* __restrict__ cams, int N) {
    __shared__ CamData cam;

    if (threadIdx.x == 0) {
        for (int i = 0; i < 3; i++)
            cam_mat(cams + i * 5, cam.c[i], cam.o[i]);

        double M[3][3];
        for (int r = 0; r < 3; r++)
            for (int k = 0; k < 3; k++)
                M[r][k] = (double)cam.c[0][k*3 + r];

        double det = M[0][0]*(M[1][1]*M[2][2] - M[1][2]*M[2][1])
                   - M[0][1]*(M[1][0]*M[2][2] - M[1][2]*M[2][0])
                   + M[0][2]*(M[1][0]*M[2][1] - M[1][1]*M[2][0]);
        double inv[3][3];
        inv[0][0] =  (M[1][1]*M[2][2] - M[1][2]*M[2][1]) / det;
        inv[0][1] =  (M[0][2]*M[2][1] - M[0][1]*M[2][2]) / det;
        inv[0][2] =  (M[0][1]*M[1][2] - M[0][2]*M[1][1]) / det;
        inv[1][0] =  (M[1][2]*M[2][0] - M[1][0]*M[2][2]) / det;
        inv[1][1] =  (M[0][0]*M[2][2] - M[0][2]*M[2][0]) / det;
        inv[1][2] =  (M[0][2]*M[1][0] - M[0][0]*M[1][2]) / det;
        inv[2][0] =  (M[1][0]*M[2][1] - M[1][1]*M[2][0]) / det;
        inv[2][1] =  (M[0][1]*M[2][0] - M[0][0]*M[2][1]) / det;
        inv[2][2] =  (M[0][0]*M[1][1] - M[0][1]*M[1][0]) / det;
        for (int k = 0; k < 3; k++)
            for (int j = 0; j < 3; j++)
                cam.B0[k*3 + j] = (float)inv[k][j];
    }
    __syncthreads();

    int p = blockIdx.x * blockDim.x + threadIdx.x;
    if (p >= N) return;

    float x = coord[p*3 + 0];
    float y = coord[p*3 + 1];
    float z = coord[p*3 + 2];

    float po[3];
    #pragma unroll
    for (int j = 0; j < 3; j++)
        po[j] = x * cam.B0[0*3 + j] + y * cam.B0[1*3 + j]
              + z * cam.B0[2*3 + j] + cam.o[0][j];

    const int   ds[4] = { 56, 28, 14, 7 };
    const int   Cs[4] = { 64, 128, 256, 512 };
    const float qi[4] = { 0.25f, 0.125f, 0.0625f, 0.03125f };  // d/224 exact pow2

    int off[12];
    #pragma unroll
    for (int i = 0; i < 3; i++) {
        float vx = po[0] - cam.o[i][0];
        float vy = po[1] - cam.o[i][1];
        float vz = po[2] - cam.o[i][2];
        const float* C = cam.c[i];
        float X  = vx*C[0] + vy*C[1] + vz*C[2];
        float Y  = vx*C[3] + vy*C[4] + vz*C[5];
        float Zc = vx*C[6] + vy*C[7] + vz*C[8];

        float negz = -Zc;
        float h = __fdiv_rn(248.0f * (-Y), negz) + 112.0f;
        float w = __fdiv_rn(248.0f * X,    negz) + 112.0f;
        h = fminf(fmaxf(h, 0.0f), 223.0f);
        w = fminf(fmaxf(w, 0.0f), 223.0f);

        #pragma unroll
        for (int s = 0; s < 4; s++) {
            int ih = (int)(h * qi[s]);
            int iw = (int)(w * qi[s]);
            off[i*4 + s] = (ih * ds[s] + iw) * Cs[s];
        }
    }
    int4* dst = reinterpret_cast<int4*>(g_off + p*12);
    dst[0] = make_int4(off[0], off[1], off[2],  off[3]);
    dst[1] = make_int4(off[4], off[5], off[6],  off[7]);
    dst[2] = make_int4(off[8], off[9], off[10], off[11]);
}

// --- kernel B: warp-per-point rolling shifted window ------------------------
__global__ __launch_bounds__(256)
void gather_kernel(const float* __restrict__ f1, const float* __restrict__ f2,
                   const float* __restrict__ f3, const float* __restrict__ f4,
                   const float* __restrict__ coord, float* __restrict__ out) {
    int wid  = threadIdx.x >> 5;
    int lane = threadIdx.x & 31;
    unsigned p = blockIdx.x * 8u + (unsigned)wid;
    unsigned g = p * (unsigned)OUT_STRIDE;              // < 2^31
    int u = (int)((32u - ((g + 3u) & 31u)) & 31u);      // g+3+u ≡ 0 (mod 32)

    int v = (lane < 12) ? g_off[p * 12u + (unsigned)lane] : 0;

    if (lane < 3) out[g + (unsigned)lane] = __ldg(coord + p * 3u + (unsigned)lane);

    int src = (lane + u) & 31;          // shuffle source for window rebuild
    bool send_prev = (lane >= u);       // lane publishes prev (else cur)

    float pm, pn, ps;                   // previous row's stats
    int k;                              // current channel row (32 ch each)

    // ---- peeled row 0 (scale 0): compute stats, store head [0,u) ----
    {
        int o0 = __shfl_sync(0xFFFFFFFFu, v, 0);
        int o1 = __shfl_sync(0xFFFFFFFFu, v, 4);
        int o2 = __shfl_sync(0xFFFFFFFFu, v, 8);
        float a = __ldg(f1 + o0 + lane);
        float b = __ldg(f1 + o1 + lane);
        float d = __ldg(f1 + o2 + lane);
        pm = fmaxf(a, fmaxf(b, d));
        pn = (a + b + d) * (1.0f / 3.0f);
        float da = a - pn, db = b - pn, dc = d - pn;
        ps = sqrtf((da*da + db*db + dc*dc) * (1.0f / 3.0f));
        if (lane < u) {
            out[g + 3u + (unsigned)lane]    = pm;
            out[g + 963u + (unsigned)lane]  = pn;
            out[g + 1923u + (unsigned)lane] = ps;
        }
        k = 1;
    }

    // ---- generic segment: rows [k, k+CNT) of scale S ----
#define SEGMENT(F, S, BASE, CNT, UNR)                                          \
    {                                                                          \
        int o0 = __shfl_sync(0xFFFFFFFFu, v, (S));                             \
        int o1 = __shfl_sync(0xFFFFFFFFu, v, 4 + (S));                         \
        int o2 = __shfl_sync(0xFFFFFFFFu, v, 8 + (S));                         \
        _Pragma(UNR)                                                           \
        for (int kk = 0; kk < (CNT); kk++) {                                   \
            int cl = (k << 5) - (BASE) + lane;                                 \
            float a = __ldg((F) + o0 + cl);                                    \
            float b = __ldg((F) + o1 + cl);                                    \
            float d = __ldg((F) + o2 + cl);                                    \
            float cm = fmaxf(a, fmaxf(b, d));                                  \
            float cn = (a + b + d) * (1.0f / 3.0f);                            \
            float da = a - cn, db = b - cn, dc = d - cn;                       \
            float cs = sqrtf((da*da + db*db + dc*dc) * (1.0f / 3.0f));         \
            float wm = __shfl_sync(0xFFFFFFFFu, send_prev ? pm : cm, src);     \
            float wn = __shfl_sync(0xFFFFFFFFu, send_prev ? pn : cn, src);     \
            float ws = __shfl_sync(0xFFFFFFFFu, send_prev ? ps : cs, src);     \
            unsigned A = g + 3u + (unsigned)(u + ((k - 1) << 5) + lane);       \
            out[A]         = wm;                                               \
            out[A + 960u]  = wn;                                               \
            out[A + 1920u] = ws;                                               \
            pm = cm; pn = cn; ps = cs; k++;                                    \
        }                                                                      \
    }

    SEGMENT(f1, 0,   0,  1, "unroll")      // row 1          (scale 0 done)
    SEGMENT(f2, 1,  64,  4, "unroll")      // rows 2..5
    SEGMENT(f3, 2, 192,  8, "unroll 4")    // rows 6..13
    SEGMENT(f4, 3, 448, 16, "unroll 4")    // rows 14..29
#undef SEGMENT

    // ---- tail: window 29 = channels [u+928, 960), from prev only ----
    {
        float wm = __shfl_sync(0xFFFFFFFFu, pm, src);
        float wn = __shfl_sync(0xFFFFFFFFu, pn, src);
        float ws = __shfl_sync(0xFFFFFFFFu, ps, src);
        if (lane < 32 - u) {
            unsigned A = g + 3u + (unsigned)(u + 928 + lane);
            out[A]         = wm;
            out[A + 960u]  = wn;
            out[A + 1920u] = ws;
        }
    }
}

extern "C" void kernel_launch(void* const* d_in, const int* in_sizes, int n_in,
                              void* d_out, int out_size) {
    const float* coord = (const float*)d_in[0];
    const float* cams  = (const float*)d_in[1];
    const float* f1    = (const float*)d_in[2];
    const float* f2    = (const float*)d_in[3];
    const float* f3    = (const float*)d_in[4];
    const float* f4    = (const float*)d_in[5];
    float* out = (float*)d_out;

    int N = in_sizes[0] / 3;

    proj_kernel<<<(N + 255) / 256, 256>>>(coord, cams, N);
    gather_kernel<<<N / 8, 256>>>(f1, f2, f3, f4, coord, out);
}